// round 11
// baseline (speedup 1.0000x reference)
#include <cuda_runtime.h>
#include <cstdint>
#include <math.h>
#include <float.h>

#define BATCH   131072
#define DIM     256
#define NCOL    208
#define NCOLP   224

#define NSLICE  7
#define NTILES  (BATCH / 128)    // 1024 tiles of 128 rows

// ---------------- scratch (device globals; no runtime alloc) ----------------
__device__ float g_logits[(size_t)BATCH * NCOLP];   // ~117 MB
__device__ float g_wpack[DIM * NCOLP];
__device__ float g_bpack[NCOLP];

// ---------------- Threefry-2x32 (JAX partitionable mode) ----------------
__host__ __device__ __forceinline__ uint32_t rotl32(uint32_t x, int r) {
    return (x << r) | (x >> (32 - r));
}

__host__ __device__ __forceinline__ void threefry2x32(
    uint32_t k0, uint32_t k1, uint32_t x0, uint32_t x1,
    uint32_t& o0, uint32_t& o1)
{
    uint32_t ks2 = 0x1BD11BDAu ^ k0 ^ k1;
    x0 += k0; x1 += k1;
#define TF_RND(r) { x0 += x1; x1 = rotl32(x1, r); x1 ^= x0; }
    TF_RND(13) TF_RND(15) TF_RND(26) TF_RND(6)   x0 += k1;  x1 += ks2 + 1u;
    TF_RND(17) TF_RND(29) TF_RND(16) TF_RND(24)  x0 += ks2; x1 += k0  + 2u;
    TF_RND(13) TF_RND(15) TF_RND(26) TF_RND(6)   x0 += k0;  x1 += k1  + 3u;
    TF_RND(17) TF_RND(29) TF_RND(16) TF_RND(24)  x0 += k1;  x1 += ks2 + 4u;
    TF_RND(13) TF_RND(15) TF_RND(26) TF_RND(6)   x0 += ks2; x1 += k0  + 5u;
#undef TF_RND
    o0 = x0; o1 = x1;
}

__device__ __forceinline__ uint32_t tf_bits_part(uint32_t k0, uint32_t k1, uint32_t j) {
    uint32_t o0, o1;
    threefry2x32(k0, k1, 0u, j, o0, o1);
    return o0 ^ o1;
}

// Exact-path gumbel: bit-identical to JAX (precise logf).
__device__ __forceinline__ float bits_to_gumbel(uint32_t bits) {
    float f = __uint_as_float((bits >> 9) | 0x3f800000u) - 1.0f;
    float u = fmaxf(1.17549435e-38f, f + 1.17549435e-38f);
    return -logf(-logf(u));
}

struct SampKeys {
    uint32_t sc[8][2];
    uint32_t pw[2];
};

// ---------------- f32x2 + cp.async helpers ----------------
typedef unsigned long long ull;

__device__ __forceinline__ ull pack2(float x) {
    ull r; asm("mov.b64 %0, {%1, %1};" : "=l"(r) : "f"(x)); return r;
}
__device__ __forceinline__ void fma2(ull& d, ull a, ull b) {
    asm("fma.rn.f32x2 %0, %1, %2, %0;" : "+l"(d) : "l"(a), "l"(b));
}
__device__ __forceinline__ void unpack2(ull v, float& lo, float& hi) {
    asm("mov.b64 {%0, %1}, %2;" : "=f"(lo), "=f"(hi) : "l"(v));
}
__device__ __forceinline__ void cp16(void* smem, const void* gmem) {
    uint32_t s = (uint32_t)__cvta_generic_to_shared(smem);
    asm volatile("cp.async.cg.shared.global [%0], [%1], 16;" :: "r"(s), "l"(gmem));
}
#define CP_COMMIT() asm volatile("cp.async.commit_group;")
#define CP_WAIT0()  asm volatile("cp.async.wait_group 0;")

// ---------------- pack kernel: W_sc/W_pow -> [D][224] ----------------
__global__ void pack_kernel(const float* __restrict__ Wsc, const float* __restrict__ bsc,
                            const float* __restrict__ Wpow, const float* __restrict__ bpow)
{
    int idx = blockIdx.x * blockDim.x + threadIdx.x;
    if (idx >= DIM * NCOLP) return;
    int d = idx / NCOLP;
    int j = idx - d * NCOLP;
    float w = 0.0f;
    if (j < 128) {
        int u = j >> 4, s = j & 15;
        w = Wsc[(u * DIM + d) * 16 + s];
    } else if (j < NCOL) {
        int jp = j - 128;
        int u = jp / 10, p = jp - u * 10;
        w = Wpow[(u * DIM + d) * 10 + p];
    }
    g_wpack[d * NCOLP + j] = w;
    if (d == 0) {
        float bb = 0.0f;
        if (j < 128)       bb = bsc[(j >> 4) * 16 + (j & 15)];
        else if (j < NCOL) { int jp = j - 128; bb = bpow[(jp / 10) * 10 + (jp % 10)]; }
        g_bpack[j] = bb;
    }
}

// ---------------- GEMM: logits[rows][224] = x @ wpack + b (unchanged) ------
#define TM 128
#define TKC 32
#define NCHUNK (DIM / TKC)   // 8

#define G_OFF_AS4 0
#define G_OFF_WS  33024
#define G_SMEM    90368

__global__ __launch_bounds__(256, 1)
void gemm_kernel(const float* __restrict__ x, int rowBase)
{
    extern __shared__ char sm[];
    float4* As4 = (float4*)(sm + G_OFF_AS4);   // [2][8][129]
    float*  Ws  = (float*)(sm + G_OFF_WS);     // [2][32][224]

    const int tid = threadIdx.x;
    const int row0 = rowBase + blockIdx.x * TM;
    const int ty = tid >> 4;
    const int tx = tid & 15;
    const int col0 = tx * 14;

    ull acc[8][7];
#pragma unroll
    for (int r = 0; r < 8; r++)
#pragma unroll
        for (int c = 0; c < 7; c++) acc[r][c] = 0ULL;

    auto issue_loads = [&](int kc, int buf) {
        const int k0 = kc * TKC;
#pragma unroll
        for (int i = 0; i < 4; i++) {
            int f = tid + i * 256;
            int row = f >> 3, q = f & 7;
            cp16(&As4[(buf * 8 + q) * 129 + row],
                 x + (size_t)(row0 + row) * DIM + k0 + q * 4);
        }
#pragma unroll
        for (int i = 0; i < 7; i++) {
            int f = tid + i * 256;
            int k = f / 56, j = f - k * 56;
            cp16(&Ws[((size_t)buf * TKC + k) * NCOLP + j * 4],
                 g_wpack + (size_t)(k0 + k) * NCOLP + j * 4);
        }
        CP_COMMIT();
    };

    issue_loads(0, 0);
    CP_WAIT0();
    __syncthreads();

    for (int kc = 0; kc < NCHUNK; kc++) {
        const int cur = kc & 1;
        if (kc + 1 < NCHUNK) issue_loads(kc + 1, cur ^ 1);

#pragma unroll
        for (int q = 0; q < 8; q++) {
            float4 a4[8];
#pragma unroll
            for (int r = 0; r < 8; r++) a4[r] = As4[(cur * 8 + q) * 129 + ty * 8 + r];
#pragma unroll
            for (int j = 0; j < 4; j++) {
                ull b2[7];
#pragma unroll
                for (int c = 0; c < 7; c++)
                    b2[c] = *(const ull*)&Ws[((size_t)cur * TKC + q * 4 + j) * NCOLP + col0 + 2 * c];
#pragma unroll
                for (int r = 0; r < 8; r++) {
                    float aj = ((const float*)&a4[r])[j];
                    ull a2 = pack2(aj);
#pragma unroll
                    for (int c = 0; c < 7; c++) fma2(acc[r][c], a2, b2[c]);
                }
            }
        }

        if (kc + 1 < NCHUNK) CP_WAIT0();
        __syncthreads();
    }

    float bb[14];
#pragma unroll
    for (int c = 0; c < 14; c++) bb[c] = g_bpack[col0 + c];

#pragma unroll
    for (int r = 0; r < 8; r++) {
        const size_t rowoff = (size_t)(row0 + ty * 8 + r) * NCOLP + col0;
#pragma unroll
        for (int c = 0; c < 7; c++) {
            float lo, hi;
            unpack2(acc[r][c], lo, hi);
            *(float2*)&g_logits[rowoff + 2 * c] = make_float2(lo + bb[2 * c], hi + bb[2 * c + 1]);
        }
    }
}

// ---------------- sampler: 128-thr CTA = 64 rows; sc/pow thread split ------
// Co-residency budget: (128,7) caps regs at 73 -> 128x80 = 10240 regs,
// exactly the leftover beside gemm's 216x256. Dynamic smem 57856 B.
#define LSTR 225
#define S_SMEM (64 * LSTR * 4 + 256)   // Ls + lps

__global__ __launch_bounds__(128, 7)
void sample_kernel(const int* __restrict__ avail, float* __restrict__ out,
                   SampKeys keys, int rowBase)
{
    extern __shared__ char ssm[];
    float* Ls  = (float*)ssm;                     // [64][225]
    float* lps = (float*)(ssm + 64 * LSTR * 4);   // [64]

    const int t = threadIdx.x;
    const int row0 = rowBase + blockIdx.x * 64;
    const float NEG = -10000000000.0f;

    // ---- stage whole 64x224 tile once (f4 gmem loads, scalar smem stores) ----
#pragma unroll
    for (int i = 0; i < 28; i++) {
        int f = t + i * 128;            // 0..3583 f4 units
        int row = f / 56, c4 = f - row * 56;
        float4 v = *(const float4*)&g_logits[(size_t)(row0 + row) * NCOLP + c4 * 4];
        float* d = Ls + row * LSTR + c4 * 4;
        d[0] = v.x; d[1] = v.y; d[2] = v.z; d[3] = v.w;
    }
    __syncthreads();

    const int r = t & 63;
    const int b = row0 + r;
    const float* L = Ls + r * LSTR;
    float lp = 0.0f;

    if (t < 64) {
        // ---- 8 sequential capacity-masked heads (16 classes) ----
        unsigned cnt = 0;
        float act[8];
#pragma unroll
        for (int u = 0; u < 8; u++) {
            const uint32_t k0 = keys.sc[u][0], k1 = keys.sc[u][1];
            int a = 0;
            float best = -INFINITY, m = -INFINITY;
            float ml[16];
#pragma unroll
            for (int c = 0; c < 16; c++) {
                ml[c] = (((cnt >> (2 * c)) & 3u) < 2u) ? L[u * 16 + c] : NEG;
                float g = bits_to_gumbel(tf_bits_part(k0, k1, (uint32_t)(b * 16 + c)));
                float z = g + ml[c];
                if (z > best) { best = z; a = c; }
                m = fmaxf(m, ml[c]);
            }
            float s = 0.0f;
#pragma unroll
            for (int c = 0; c < 16; c++) s += __expf(ml[c] - m);
            float lg = (ml[a] - m) - __logf(s);
            int av = avail[b * 16 + u];
            act[u] = (av > 0) ? (float)a : -1.0f;
            if (av > 0) { lp += lg; cnt += 1u << (2 * a); }
        }
        *(float4*)&out[(size_t)b * 16 + 0] = make_float4(act[0], act[1], act[2], act[3]);
        *(float4*)&out[(size_t)b * 16 + 4] = make_float4(act[4], act[5], act[6], act[7]);
    } else {
        // ---- 8 power heads (10 classes) ----
        float act[8];
#pragma unroll
        for (int h = 0; h < 8; h++) {
            const float* Lp = L + 128 + h * 10;
            int a = 0;
            float best = -INFINITY, m = -INFINITY;
#pragma unroll
            for (int k = 0; k < 10; k++) {
                float g = bits_to_gumbel(tf_bits_part(keys.pw[0], keys.pw[1],
                                                      (uint32_t)(b * 80 + h * 10 + k)));
                float z = g + Lp[k];
                if (z > best) { best = z; a = k; }
                m = fmaxf(m, Lp[k]);
            }
            float s = 0.0f;
#pragma unroll
            for (int k = 0; k < 10; k++) s += __expf(Lp[k] - m);
            float lg = (Lp[a] - m) - __logf(s);
            int av = avail[b * 16 + 8 + h];
            act[h] = (av > 0) ? (float)a : -1.0f;
            if (av > 0) lp += lg;
        }
        *(float4*)&out[(size_t)b * 16 + 8]  = make_float4(act[0], act[1], act[2], act[3]);
        *(float4*)&out[(size_t)b * 16 + 12] = make_float4(act[4], act[5], act[6], act[7]);
        lps[r] = lp;
    }
    __syncthreads();

    const size_t OFF = (size_t)BATCH * 17;
    if (t < 64) {
        out[(size_t)BATCH * 16 + b] = lp + lps[r];
        int4 v0 = *(const int4*)&avail[b * 16 + 0];
        int4 v1 = *(const int4*)&avail[b * 16 + 4];
        *(float4*)&out[OFF + (size_t)b * 16 + 0] =
            make_float4((float)v0.x, (float)v0.y, (float)v0.z, (float)v0.w);
        *(float4*)&out[OFF + (size_t)b * 16 + 4] =
            make_float4((float)v1.x, (float)v1.y, (float)v1.z, (float)v1.w);
    } else {
        int4 v0 = *(const int4*)&avail[b * 16 + 8];
        int4 v1 = *(const int4*)&avail[b * 16 + 12];
        *(float4*)&out[OFF + (size_t)b * 16 + 8] =
            make_float4((float)v0.x, (float)v0.y, (float)v0.z, (float)v0.w);
        *(float4*)&out[OFF + (size_t)b * 16 + 12] =
            make_float4((float)v1.x, (float)v1.y, (float)v1.z, (float)v1.w);
    }
}

// ---------------- host: interleaved single-wave slices, priority stream ----
static cudaStream_t g_s2 = nullptr;
static cudaEvent_t  g_ev[NSLICE];
static cudaEvent_t  g_join;

extern "C" void kernel_launch(void* const* d_in, const int* in_sizes, int n_in,
                              void* d_out, int out_size)
{
    const float* x     = (const float*)d_in[0];
    const int*   avail = (const int*)  d_in[1];
    const float* Wsc   = (const float*)d_in[2];
    const float* bsc   = (const float*)d_in[3];
    const float* Wpow  = (const float*)d_in[4];
    const float* bpow  = (const float*)d_in[5];
    float* out = (float*)d_out;

    if (g_s2 == nullptr) {
        int lo = 0, hi = 0;
        cudaDeviceGetStreamPriorityRange(&lo, &hi);   // hi = greatest priority
        cudaStreamCreateWithPriority(&g_s2, cudaStreamNonBlocking, hi);
        for (int i = 0; i < NSLICE; i++)
            cudaEventCreateWithFlags(&g_ev[i], cudaEventDisableTiming);
        cudaEventCreateWithFlags(&g_join, cudaEventDisableTiming);
    }

    // JAX key(42) -> [0,42]; partitionable fold-like split + fold_in.
    SampKeys keys;
    for (int u = 0; u < 8; u++) {
        uint32_t o0, o1;
        threefry2x32(0u, 42u, 0u, (uint32_t)u, o0, o1);
        keys.sc[u][0] = o0; keys.sc[u][1] = o1;
    }
    threefry2x32(0u, 42u, 0u, 999u, keys.pw[0], keys.pw[1]);

    cudaFuncSetAttribute(gemm_kernel, cudaFuncAttributeMaxDynamicSharedMemorySize, G_SMEM);
    cudaFuncSetAttribute(sample_kernel, cudaFuncAttributeMaxDynamicSharedMemorySize, S_SMEM);

    pack_kernel<<<(DIM * NCOLP + 255) / 256, 256>>>(Wsc, bsc, Wpow, bpow);

    // Interleaved creation order: g0,e0,s0,g1,e1,s1,... so sampler slice s
    // precedes gemm slice s+1 in node order when both become ready.
    int base = 0;
    for (int s = 0; s < NSLICE; s++) {
        int tiles = (s < NSLICE - 1) ? 148 : (NTILES - 148 * (NSLICE - 1));  // 148x6 + 136
        gemm_kernel<<<tiles, 256, G_SMEM, 0>>>(x, base * TM);
        cudaEventRecord(g_ev[s], 0);
        cudaStreamWaitEvent(g_s2, g_ev[s], 0);
        sample_kernel<<<tiles * 2, 128, S_SMEM, g_s2>>>(avail, out, keys, base * TM);
        base += tiles;
    }
    cudaEventRecord(g_join, g_s2);
    cudaStreamWaitEvent(0, g_join, 0);
}

// round 12
// speedup vs baseline: 1.7030x; 1.7030x over previous
#include <cuda_runtime.h>
#include <cstdint>
#include <math.h>
#include <float.h>

#define BATCH   131072
#define DIM     256
#define NCOL    208
#define NCOLP   224
#define NTILES  (BATCH / 128)    // 1024

// ---------------- scratch (device globals; no runtime alloc) ----------------
__device__ float g_logits[(size_t)BATCH * NCOLP];   // ~117 MB
__device__ float g_wpack[DIM * NCOLP];
__device__ float g_bpack[NCOLP];

// ---------------- Threefry-2x32 (JAX partitionable mode) ----------------
__host__ __device__ __forceinline__ uint32_t rotl32(uint32_t x, int r) {
    return (x << r) | (x >> (32 - r));
}

__host__ __device__ __forceinline__ void threefry2x32(
    uint32_t k0, uint32_t k1, uint32_t x0, uint32_t x1,
    uint32_t& o0, uint32_t& o1)
{
    uint32_t ks2 = 0x1BD11BDAu ^ k0 ^ k1;
    x0 += k0; x1 += k1;
#define TF_RND(r) { x0 += x1; x1 = rotl32(x1, r); x1 ^= x0; }
    TF_RND(13) TF_RND(15) TF_RND(26) TF_RND(6)   x0 += k1;  x1 += ks2 + 1u;
    TF_RND(17) TF_RND(29) TF_RND(16) TF_RND(24)  x0 += ks2; x1 += k0  + 2u;
    TF_RND(13) TF_RND(15) TF_RND(26) TF_RND(6)   x0 += k0;  x1 += k1  + 3u;
    TF_RND(17) TF_RND(29) TF_RND(16) TF_RND(24)  x0 += k1;  x1 += ks2 + 4u;
    TF_RND(13) TF_RND(15) TF_RND(26) TF_RND(6)   x0 += ks2; x1 += k0  + 5u;
#undef TF_RND
    o0 = x0; o1 = x1;
}

__device__ __forceinline__ uint32_t tf_bits_part(uint32_t k0, uint32_t k1, uint32_t j) {
    uint32_t o0, o1;
    threefry2x32(k0, k1, 0u, j, o0, o1);
    return o0 ^ o1;
}

// Exact-path gumbel: bit-identical to JAX (precise logf).
__device__ __forceinline__ float bits_to_gumbel(uint32_t bits) {
    float f = __uint_as_float((bits >> 9) | 0x3f800000u) - 1.0f;
    float u = fmaxf(1.17549435e-38f, f + 1.17549435e-38f);
    return -logf(-logf(u));
}

struct SampKeys {
    uint32_t sc[8][2];
    uint32_t pw[2];
};

// ---------------- f32x2 + cp.async helpers ----------------
typedef unsigned long long ull;

__device__ __forceinline__ ull pack2(float x) {
    ull r; asm("mov.b64 %0, {%1, %1};" : "=l"(r) : "f"(x)); return r;
}
__device__ __forceinline__ void fma2(ull& d, ull a, ull b) {
    asm("fma.rn.f32x2 %0, %1, %2, %0;" : "+l"(d) : "l"(a), "l"(b));
}
__device__ __forceinline__ void unpack2(ull v, float& lo, float& hi) {
    asm("mov.b64 {%0, %1}, %2;" : "=f"(lo), "=f"(hi) : "l"(v));
}
__device__ __forceinline__ void cp16(void* smem, const void* gmem) {
    uint32_t s = (uint32_t)__cvta_generic_to_shared(smem);
    asm volatile("cp.async.cg.shared.global [%0], [%1], 16;" :: "r"(s), "l"(gmem));
}
#define CP_COMMIT() asm volatile("cp.async.commit_group;")
#define CP_WAIT0()  asm volatile("cp.async.wait_group 0;")

// ---------------- pack kernel: W_sc/W_pow -> [D][224] ----------------
__global__ void pack_kernel(const float* __restrict__ Wsc, const float* __restrict__ bsc,
                            const float* __restrict__ Wpow, const float* __restrict__ bpow)
{
    int idx = blockIdx.x * blockDim.x + threadIdx.x;
    if (idx >= DIM * NCOLP) return;
    int d = idx / NCOLP;
    int j = idx - d * NCOLP;
    float w = 0.0f;
    if (j < 128) {
        int u = j >> 4, s = j & 15;
        w = Wsc[(u * DIM + d) * 16 + s];
    } else if (j < NCOL) {
        int jp = j - 128;
        int u = jp / 10, p = jp - u * 10;
        w = Wpow[(u * DIM + d) * 10 + p];
    }
    g_wpack[d * NCOLP + j] = w;
    if (d == 0) {
        float bb = 0.0f;
        if (j < 128)       bb = bsc[(j >> 4) * 16 + (j & 15)];
        else if (j < NCOL) { int jp = j - 128; bb = bpow[(jp / 10) * 10 + (jp % 10)]; }
        g_bpack[j] = bb;
    }
}

// ---------------- GEMM: split-N, 2 CTAs per 128-row tile, 2 CTAs/SM --------
// Half 0: cols 0..111 (NF4=28), half 1: cols 112..207 (NF4=24).
// Thread (ty,tx): ty=tid>>3 owns 4 rows; tx=tid&7 owns NCOLS/8 cols.
#define TKC 32
#define NCHUNK (DIM / TKC)   // 8

#define G_OFF_AS4 0          // float4[2][8][129] = 33024 B
#define G_OFF_WS  33024      // float [2][32][112] = 28672 B (max)
#define G_SMEM    61696

template<int NF4>            // f4 per W row: 28 (112 cols) or 24 (96 cols)
__device__ __forceinline__ void gemm_body(const float* __restrict__ x,
                                          char* sm, int tile, int halfBase)
{
    constexpr int NCOLS = NF4 * 4;      // 112 or 96
    constexpr int PT    = NCOLS / 8;    // cols per thread: 14 or 12
    constexpr int NU    = PT / 2;       // ulls per thread: 7 or 6

    float4* As4 = (float4*)(sm + G_OFF_AS4);   // [2][8][129]
    float*  Ws  = (float*)(sm + G_OFF_WS);     // [2][32][NCOLS]

    const int tid = threadIdx.x;
    const int row0 = tile * 128;
    const int ty = tid >> 3;            // 0..31 -> 4 rows each
    const int tx = tid & 7;             // 0..7  -> PT cols each
    const int col0 = tx * PT;           // local col (even -> ull aligned)

    ull acc[4][NU];
#pragma unroll
    for (int r = 0; r < 4; r++)
#pragma unroll
        for (int c = 0; c < NU; c++) acc[r][c] = 0ULL;

    auto issue_loads = [&](int kc, int buf) {
        const int k0 = kc * TKC;
        // x: 128 rows x 8 f4 = 1024 f4, 4 per thread
#pragma unroll
        for (int i = 0; i < 4; i++) {
            int f = tid + i * 256;
            int row = f >> 3, q = f & 7;
            cp16(&As4[(buf * 8 + q) * 129 + row],
                 x + (size_t)(row0 + row) * DIM + k0 + q * 4);
        }
        // w half: 32 * NF4 f4
#pragma unroll
        for (int i = 0; i < 4; i++) {
            int f = tid + i * 256;
            if (f < 32 * NF4) {
                int k = f / NF4, j = f - k * NF4;
                cp16(&Ws[(buf * 32 + k) * NCOLS + j * 4],
                     g_wpack + (size_t)(k0 + k) * NCOLP + halfBase + j * 4);
            }
        }
        CP_COMMIT();
    };

    issue_loads(0, 0);
    CP_WAIT0();
    __syncthreads();

    for (int kc = 0; kc < NCHUNK; kc++) {
        const int cur = kc & 1;
        if (kc + 1 < NCHUNK) issue_loads(kc + 1, cur ^ 1);

#pragma unroll
        for (int q = 0; q < 8; q++) {
            float4 a4[4];
#pragma unroll
            for (int r = 0; r < 4; r++) a4[r] = As4[(cur * 8 + q) * 129 + ty * 4 + r];
#pragma unroll
            for (int j = 0; j < 4; j++) {
                ull b2[NU];
#pragma unroll
                for (int c = 0; c < NU; c++)
                    b2[c] = *(const ull*)&Ws[(cur * 32 + q * 4 + j) * NCOLS + col0 + 2 * c];
#pragma unroll
                for (int r = 0; r < 4; r++) {
                    float aj = ((const float*)&a4[r])[j];
                    ull a2 = pack2(aj);
#pragma unroll
                    for (int c = 0; c < NU; c++) fma2(acc[r][c], a2, b2[c]);
                }
            }
        }

        if (kc + 1 < NCHUNK) CP_WAIT0();
        __syncthreads();
    }

    // epilogue: + bias, store float2
    float bb[PT];
#pragma unroll
    for (int c = 0; c < PT; c++) bb[c] = g_bpack[halfBase + col0 + c];

#pragma unroll
    for (int r = 0; r < 4; r++) {
        const size_t rowoff = (size_t)(row0 + ty * 4 + r) * NCOLP + halfBase + col0;
#pragma unroll
        for (int c = 0; c < NU; c++) {
            float lo, hi;
            unpack2(acc[r][c], lo, hi);
            *(float2*)&g_logits[rowoff + 2 * c] = make_float2(lo + bb[2 * c], hi + bb[2 * c + 1]);
        }
    }
}

__global__ __launch_bounds__(256, 2)
void gemm_kernel(const float* __restrict__ x)
{
    extern __shared__ char sm[];
    const int tile = blockIdx.x >> 1;
    if ((blockIdx.x & 1) == 0) gemm_body<28>(x, sm, tile, 0);
    else                       gemm_body<24>(x, sm, tile, 112);
}

// ---------------- sampler: one thread per batch row, smem-staged (R6) ------
__global__ __launch_bounds__(256)
void sample_kernel(const int* __restrict__ avail, float* __restrict__ out, SampKeys keys)
{
    __shared__ float Ls[256][18];

    const int t = threadIdx.x;
    const int row0 = blockIdx.x * 256;
    const int b = row0 + t;

    const float NEG = -10000000000.0f;
    unsigned cnt = 0;
    float lp = 0.0f;

    // ---- 8 sequential capacity-masked heads (16 classes) ----
    for (int u = 0; u < 8; u++) {
        __syncthreads();
#pragma unroll
        for (int i = 0; i < 4; i++) {
            int e4 = t + i * 256;
            int row = e4 >> 2, c4 = e4 & 3;
            float4 v = *(const float4*)&g_logits[(size_t)(row0 + row) * NCOLP + u * 16 + c4 * 4];
            *(float2*)&Ls[row][c4 * 4]     = make_float2(v.x, v.y);
            *(float2*)&Ls[row][c4 * 4 + 2] = make_float2(v.z, v.w);
        }
        __syncthreads();
        const float* L = Ls[t];

        const uint32_t k0 = keys.sc[u][0], k1 = keys.sc[u][1];
        int a = 0;
        float best = -INFINITY, m = -INFINITY;
        float ml[16];
#pragma unroll
        for (int c = 0; c < 16; c++) {
            ml[c] = (((cnt >> (2 * c)) & 3u) < 2u) ? L[c] : NEG;
            float g = bits_to_gumbel(tf_bits_part(k0, k1, (uint32_t)(b * 16 + c)));
            float z = g + ml[c];
            if (z > best) { best = z; a = c; }
            m = fmaxf(m, ml[c]);
        }
        float s = 0.0f;
#pragma unroll
        for (int c = 0; c < 16; c++) s += __expf(ml[c] - m);
        float lg = (ml[a] - m) - __logf(s);
        int av = avail[b * 16 + u];
        out[(size_t)b * 16 + u] = (av > 0) ? (float)a : -1.0f;
        if (av > 0) { lp += lg; cnt += 1u << (2 * a); }
    }

    // ---- 8 power heads (10 classes) ----
    for (int h = 0; h < 8; h++) {
        __syncthreads();
#pragma unroll
        for (int i = 0; i < 5; i++) {
            int e2 = t + i * 256;
            int row = e2 / 5, c2 = e2 - row * 5;
            float2 v = *(const float2*)&g_logits[(size_t)(row0 + row) * NCOLP + 128 + h * 10 + c2 * 2];
            *(float2*)&Ls[row][c2 * 2] = v;
        }
        __syncthreads();
        const float* L = Ls[t];

        int a = 0;
        float best = -INFINITY, m = -INFINITY;
#pragma unroll
        for (int k = 0; k < 10; k++) {
            float g = bits_to_gumbel(tf_bits_part(keys.pw[0], keys.pw[1],
                                                  (uint32_t)(b * 80 + h * 10 + k)));
            float z = g + L[k];
            if (z > best) { best = z; a = k; }
            m = fmaxf(m, L[k]);
        }
        float s = 0.0f;
#pragma unroll
        for (int k = 0; k < 10; k++) s += __expf(L[k] - m);
        float lg = (L[a] - m) - __logf(s);
        int av = avail[b * 16 + 8 + h];
        out[(size_t)b * 16 + 8 + h] = (av > 0) ? (float)a : -1.0f;
        if (av > 0) lp += lg;
    }

    out[(size_t)BATCH * 16 + b] = lp;

    const size_t OFF = (size_t)BATCH * 17;
#pragma unroll
    for (int i = 0; i < 4; i++) {
        int4 v = *(const int4*)&avail[b * 16 + i * 4];
        *(float4*)&out[OFF + (size_t)b * 16 + i * 4] =
            make_float4((float)v.x, (float)v.y, (float)v.z, (float)v.w);
    }
}

// ---------------- host ----------------
extern "C" void kernel_launch(void* const* d_in, const int* in_sizes, int n_in,
                              void* d_out, int out_size)
{
    const float* x     = (const float*)d_in[0];
    const int*   avail = (const int*)  d_in[1];
    const float* Wsc   = (const float*)d_in[2];
    const float* bsc   = (const float*)d_in[3];
    const float* Wpow  = (const float*)d_in[4];
    const float* bpow  = (const float*)d_in[5];
    float* out = (float*)d_out;

    // JAX key(42) -> [0,42]; partitionable fold-like split + fold_in.
    SampKeys keys;
    for (int u = 0; u < 8; u++) {
        uint32_t o0, o1;
        threefry2x32(0u, 42u, 0u, (uint32_t)u, o0, o1);
        keys.sc[u][0] = o0; keys.sc[u][1] = o1;
    }
    threefry2x32(0u, 42u, 0u, 999u, keys.pw[0], keys.pw[1]);

    cudaFuncSetAttribute(gemm_kernel, cudaFuncAttributeMaxDynamicSharedMemorySize, G_SMEM);

    pack_kernel<<<(DIM * NCOLP + 255) / 256, 256>>>(Wsc, bsc, Wpow, bpow);
    gemm_kernel<<<NTILES * 2, 256, G_SMEM>>>(x);
    sample_kernel<<<BATCH / 256, 256>>>(avail, out, keys);
}